// round 16
// baseline (speedup 1.0000x reference)
#include <cuda_runtime.h>
#include <cuda_bf16.h>
#include <cstdint>

#define HW   4096
#define CIN  256
#define NB   2

// ---------------- device scratch ----------------
__device__ float g_y[6 * 96 * HW];
__device__ float g_Z[10 * HW];
__device__ float g_vec[16 * HW];
// bf16 split: t = (xi*2+b)*2 + role; role0=Q(*log2e), role1=K; row=[hi32|lo32]
__device__ __nv_bfloat16 g_T[12][HW][64];

static __device__ const int QX[5] = {0, 0, 1, 2, 1};
static __device__ const int KX[5] = {1, 2, 2, 1, 0};

__device__ __forceinline__ float ex2(float x) {
    float y; asm("ex2.approx.f32 %0, %1;" : "=f"(y) : "f"(x)); return y;
}
__device__ __forceinline__ void mma16816(float* d, const uint32_t* a, uint32_t b0, uint32_t b1) {
    asm volatile("mma.sync.aligned.m16n8k16.row.col.f32.bf16.bf16.f32 "
                 "{%0,%1,%2,%3}, {%4,%5,%6,%7}, {%8,%9}, {%0,%1,%2,%3};"
                 : "+f"(d[0]), "+f"(d[1]), "+f"(d[2]), "+f"(d[3])
                 : "r"(a[0]), "r"(a[1]), "r"(a[2]), "r"(a[3]), "r"(b0), "r"(b1));
}
__device__ __forceinline__ void ldsm4(uint32_t* r, uint32_t a) {
    asm volatile("ldmatrix.sync.aligned.m8n8.x4.shared.b16 {%0,%1,%2,%3}, [%4];"
                 : "=r"(r[0]), "=r"(r[1]), "=r"(r[2]), "=r"(r[3]) : "r"(a));
}
#define CP16(d, s)  asm volatile("cp.async.cg.shared.global [%0], [%1], 16;" :: "r"(d), "l"(s))
#define CPCOMMIT()  asm volatile("cp.async.commit_group;")
#define CPWAIT1()   asm volatile("cp.async.wait_group 1;" ::: "memory")
#define CPWAIT0()   asm volatile("cp.async.wait_group 0;" ::: "memory")

#define STAGE_B 22528   // 128 rows * 176 bytes

// 6 MMAs as 3 independent depth-2 chains; e[i] = exp2 of summed logit
#define LOGIT6(c1, c2, c3, afr, bh, bl)            \
    do {                                           \
        mma16816(c1, afr[0][0], bh[0], bh[1]);     \
        mma16816(c2, afr[0][1], bh[2], bh[3]);     \
        mma16816(c3, afr[1][0], bh[0], bh[1]);     \
        mma16816(c1, afr[0][0], bl[0], bl[1]);     \
        mma16816(c2, afr[0][1], bl[2], bl[3]);     \
        mma16816(c3, afr[1][1], bh[2], bh[3]);     \
    } while (0)

// ---------------- projection (float4 loads, padded sW) ----------------
__global__ void __launch_bounds__(256) proj_kernel(
    const float* __restrict__ x1, const float* __restrict__ x2, const float* __restrict__ x3,
    const float* __restrict__ W1, const float* __restrict__ W2, const float* __restrict__ W3)
{
    int tile = blockIdx.x;
    int xb   = blockIdx.y;
    int xi = xb >> 1, b = xb & 1;
    const float* x = (xi == 0 ? x1 : xi == 1 ? x2 : x3) + (size_t)b * CIN * HW;

    __shared__ float sW[96][33];
    __shared__ float sX[32][128];

    int tid = threadIdx.x, tx = tid & 15, ty = tid >> 4;
    int hw0 = tile * 128;

    float acc[6][8];
    #pragma unroll
    for (int r = 0; r < 6; r++)
        #pragma unroll
        for (int c = 0; c < 8; c++) acc[r][c] = 0.f;

    for (int k0 = 0; k0 < CIN; k0 += 32) {
        __syncthreads();
        for (int i = tid; i < 96 * 8; i += 256) {
            int r = i >> 3, k4 = (i & 7) * 4;
            const float* Wp = (r < 32) ? W1 : (r < 64) ? W2 : W3;
            float4 v = *(const float4*)&Wp[(r & 31) * CIN + k0 + k4];
            sW[r][k4] = v.x; sW[r][k4 + 1] = v.y; sW[r][k4 + 2] = v.z; sW[r][k4 + 3] = v.w;
        }
        for (int i = tid; i < 32 * 32; i += 256) {
            int k = i >> 5, c4 = (i & 31) * 4;
            float4 v = *(const float4*)&x[(size_t)(k0 + k) * HW + hw0 + c4];
            *(float4*)&sX[k][c4] = v;
        }
        __syncthreads();
        #pragma unroll
        for (int k = 0; k < 32; k++) {
            float a[6], bb[8];
            #pragma unroll
            for (int r = 0; r < 6; r++) a[r] = sW[ty + 16 * r][k];
            #pragma unroll
            for (int c = 0; c < 8; c++) bb[c] = sX[k][tx + 16 * c];
            #pragma unroll
            for (int r = 0; r < 6; r++)
                #pragma unroll
                for (int c = 0; c < 8; c++) acc[r][c] = fmaf(a[r], bb[c], acc[r][c]);
        }
    }
    float* yp = g_y + (size_t)xb * 96 * HW;
    #pragma unroll
    for (int r = 0; r < 6; r++)
        #pragma unroll
        for (int c = 0; c < 8; c++)
            yp[(size_t)(ty + 16 * r) * HW + hw0 + tx + 16 * c] = acc[r][c];
}

// ---------------- instance norm + ReLU + V out + zero accums (float4) ----------------
__global__ void __launch_bounds__(256) instnorm_kernel(
    const float* __restrict__ g1, const float* __restrict__ b1,
    const float* __restrict__ g2, const float* __restrict__ b2,
    const float* __restrict__ g3, const float* __restrict__ b3,
    float* __restrict__ out)
{
    int id = blockIdx.x;
    int xb = id / 96, ch = id % 96;
    int xi = xb >> 1, b = xb & 1;
    float* row = g_y + (size_t)id * HW;
    float4* rowv = (float4*)row;
    int tid = threadIdx.x;

    {
        int n = 10 * HW + 16 * HW;
        for (int i = id * 256 + tid; i < n; i += 576 * 256) {
            if (i < 10 * HW) g_Z[i] = 0.f;
            else             g_vec[i - 10 * HW] = 0.f;
        }
    }

    float s = 0.f, s2 = 0.f;
    #pragma unroll
    for (int i = tid; i < HW / 4; i += 256) {
        float4 v = rowv[i];
        s += (v.x + v.y) + (v.z + v.w);
        s2 += (v.x * v.x + v.y * v.y) + (v.z * v.z + v.w * v.w);
    }
    #pragma unroll
    for (int o = 16; o; o >>= 1) {
        s  += __shfl_xor_sync(0xffffffffu, s,  o);
        s2 += __shfl_xor_sync(0xffffffffu, s2, o);
    }
    __shared__ float sh[16];
    __shared__ float sp[2];
    int w = tid >> 5;
    if ((tid & 31) == 0) { sh[w] = s; sh[8 + w] = s2; }
    __syncthreads();
    if (tid == 0) {
        float S = 0.f, S2 = 0.f;
        for (int k = 0; k < 8; k++) { S += sh[k]; S2 += sh[8 + k]; }
        float mean = S * (1.f / HW);
        float var  = S2 * (1.f / HW) - mean * mean;
        int br = ch / 32, c = ch & 31;
        const float* gp = br == 0 ? g1 : br == 1 ? g2 : g3;
        const float* bp = br == 0 ? b1 : br == 1 ? b2 : b3;
        float sc = gp[c] * rsqrtf(var + 1e-5f);
        sp[0] = sc;
        sp[1] = bp[c] - mean * sc;
    }
    __syncthreads();
    float sc = sp[0], sf = sp[1];
    bool isv = (ch >= 64);
    float4* voutv = (float4*)(out + (size_t)(5 + xi) * NB * 32 * HW + (size_t)b * 32 * HW
                              + (size_t)(ch - 64) * HW);
    #pragma unroll
    for (int i = tid; i < HW / 4; i += 256) {
        float4 v = rowv[i];
        v.x = fmaxf(fmaf(v.x, sc, sf), 0.f);
        v.y = fmaxf(fmaf(v.y, sc, sf), 0.f);
        v.z = fmaxf(fmaf(v.z, sc, sf), 0.f);
        v.w = fmaxf(fmaf(v.w, sc, sf), 0.f);
        rowv[i] = v;
        if (isv) voutv[i] = v;
    }
}

// ---------------- bf16 hi/lo split (float4 global loads) ----------------
__global__ void __launch_bounds__(256) split_kernel() {
    int xb = blockIdx.y;
    int i0 = blockIdx.x * 128;
    __shared__ float s[64][129];
    const float* src = g_y + (size_t)xb * 96 * HW;
    for (int idx = threadIdx.x; idx < 64 * 32; idx += 256) {
        int ch = idx >> 5, i = (idx & 31) * 4;
        float4 v = *(const float4*)&src[(size_t)ch * HW + i0 + i];
        s[ch][i] = v.x; s[ch][i + 1] = v.y; s[ch][i + 2] = v.z; s[ch][i + 3] = v.w;
    }
    __syncthreads();
    const float LOG2E = 1.4426950408889634f;
    for (int idx = threadIdx.x; idx < 128 * 32; idx += 256) {
        int r = idx >> 5, c = idx & 31;
        float q = s[c][r] * LOG2E;
        __nv_bfloat16 qh = __float2bfloat16(q);
        __nv_bfloat16 ql = __float2bfloat16(q - __bfloat162float(qh));
        __nv_bfloat16* qrow = &g_T[xb * 2 + 0][i0 + r][0];
        qrow[c] = qh; qrow[32 + c] = ql;
        float kv = s[32 + c][r];
        __nv_bfloat16 kh = __float2bfloat16(kv);
        __nv_bfloat16 kl = __float2bfloat16(kv - __bfloat162float(kh));
        __nv_bfloat16* krow = &g_T[xb * 2 + 1][i0 + r][0];
        krow[c] = kh; krow[32 + c] = kl;
    }
}

// ---------------- Z pass: grid (32 row tiles, 8 col groups, 10 mb) ----------------
__global__ void __launch_bounds__(256) zt2_kernel() {
    __shared__ __nv_bfloat16 sK[2][128][88];   // double buffer, 176B rows

    int tid = threadIdx.x, wid = tid >> 5, lane = tid & 31;
    int q = lane & 3, g = lane >> 2;
    int mb = blockIdx.z, m = mb >> 1, b = mb & 1;
    int r0 = blockIdx.x * 128, c0 = blockIdx.y * 512;     // 4 tiles of 128 cols

    const __nv_bfloat16 (*Qt)[64] = g_T[(QX[m] * 2 + b) * 2 + 0];
    const __nv_bfloat16 (*Kt)[64] = g_T[(KX[m] * 2 + b) * 2 + 1];

    int rw = r0 + wid * 16;
    uint32_t afr[2][2][4];
    #pragma unroll
    for (int p = 0; p < 2; p++)
        #pragma unroll
        for (int c = 0; c < 2; c++) {
            int col = p * 32 + c * 16 + q * 2;
            afr[p][c][0] = *(const uint32_t*)&Qt[rw + g][col];
            afr[p][c][1] = *(const uint32_t*)&Qt[rw + g + 8][col];
            afr[p][c][2] = *(const uint32_t*)&Qt[rw + g][col + 8];
            afr[p][c][3] = *(const uint32_t*)&Qt[rw + g + 8][col + 8];
        }

    uint32_t sbase = (uint32_t)__cvta_generic_to_shared(&sK[0][0][0]);
    int crow = tid >> 3, cc16 = tid & 7;

    #pragma unroll
    for (int k = 0; k < 4; k++) {
        int row = crow + k * 32;
        CP16(sbase + row * 176 + cc16 * 16,
             (const char*)&Kt[c0 + row][0] + cc16 * 16);
    }
    CPCOMMIT();

    float za0 = 0.f, za1 = 0.f;
    uint32_t lbase = sbase + (lane & 7) * 176 + (lane >> 3) * 16;

    for (int t = 0; t < 4; t++) {
        if (t < 3) {
            int buf = (t + 1) & 1;
            #pragma unroll
            for (int k = 0; k < 4; k++) {
                int row = crow + k * 32;
                CP16(sbase + buf * STAGE_B + row * 176 + cc16 * 16,
                     (const char*)&Kt[c0 + (t + 1) * 128 + row][0] + cc16 * 16);
            }
            CPCOMMIT();
            CPWAIT1();
        } else {
            CPWAIT0();
        }
        __syncthreads();
        uint32_t tb = lbase + (t & 1) * STAGE_B;
        #pragma unroll
        for (int nt = 0; nt < 16; nt++) {
            uint32_t bh[4], bl[4];
            uint32_t a = tb + nt * (8 * 176);
            ldsm4(bh, a);
            ldsm4(bl, a + 64);
            float c1[4] = {0.f, 0.f, 0.f, 0.f};
            float c2[4] = {0.f, 0.f, 0.f, 0.f};
            float c3[4] = {0.f, 0.f, 0.f, 0.f};
            LOGIT6(c1, c2, c3, afr, bh, bl);
            float e0 = ex2((c1[0] + c2[0]) + c3[0]);
            float e1 = ex2((c1[1] + c2[1]) + c3[1]);
            float e2 = ex2((c1[2] + c2[2]) + c3[2]);
            float e3 = ex2((c1[3] + c2[3]) + c3[3]);
            za0 += e0 + e1;
            za1 += e2 + e3;
        }
        __syncthreads();
    }
    za0 += __shfl_xor_sync(0xffffffffu, za0, 1);
    za0 += __shfl_xor_sync(0xffffffffu, za0, 2);
    za1 += __shfl_xor_sync(0xffffffffu, za1, 1);
    za1 += __shfl_xor_sync(0xffffffffu, za1, 2);
    if (q == 0) {
        atomicAdd(&g_Z[(size_t)mb * HW + rw + g], za0);
        atomicAdd(&g_Z[(size_t)mb * HW + rw + g + 8], za1);
    }
}

// ---------------- weighted colsum: grid (32 j-strips, 16 row groups, 2|4) ----------------
// m < 0: paired mode — blockIdx.z encodes (mm,b), colsum-only into vec mm (A12/A13).
__global__ void __launch_bounds__(256) bt2_kernel(int m, int w0, int o0i, int w1, int o1i) {
    __shared__ __nv_bfloat16 sQ[2][128][88];
    __shared__ float cs0[2][128];
    __shared__ float cs1[2][128];

    int tid = threadIdx.x, wid = tid >> 5, lane = tid & 31;
    int q = lane & 3, g = lane >> 2;
    int b;
    if (m < 0) {
        int mz = blockIdx.z;
        b = mz & 1;
        m = mz >> 1;
        w0 = -1; o0i = m; o1i = -1;
    } else {
        b = blockIdx.z;
    }
    int j0 = blockIdx.x * 128, rbase = blockIdx.y * 256;   // 2 tiles of 128 rows
    bool use1 = (o1i >= 0);
    size_t zoff = (size_t)(m * 2 + b) * HW;

    const __nv_bfloat16 (*Qt)[64] = g_T[(QX[m] * 2 + b) * 2 + 0];
    const __nv_bfloat16 (*Kt)[64] = g_T[(KX[m] * 2 + b) * 2 + 1];

    int jw = j0 + wid * 16;
    uint32_t afr[2][2][4];
    #pragma unroll
    for (int p = 0; p < 2; p++)
        #pragma unroll
        for (int c = 0; c < 2; c++) {
            int col = p * 32 + c * 16 + q * 2;
            afr[p][c][0] = *(const uint32_t*)&Kt[jw + g][col];
            afr[p][c][1] = *(const uint32_t*)&Kt[jw + g + 8][col];
            afr[p][c][2] = *(const uint32_t*)&Kt[jw + g][col + 8];
            afr[p][c][3] = *(const uint32_t*)&Kt[jw + g + 8][col + 8];
        }

    uint32_t sbase = (uint32_t)__cvta_generic_to_shared(&sQ[0][0][0]);
    int crow = tid >> 3, cc16 = tid & 7;

    #pragma unroll
    for (int k = 0; k < 4; k++) {
        int row = crow + k * 32;
        CP16(sbase + row * 176 + cc16 * 16,
             (const char*)&Qt[rbase + row][0] + cc16 * 16);
    }
    CPCOMMIT();

    float pc = 0.f;
    {
        int r = rbase + (tid & 127);
        float Zv = g_Z[zoff + r];
        if (tid < 128) pc = __fdividef((w0 < 0) ? 1.f : g_vec[(size_t)(w0 * 2 + b) * HW + r], Zv);
        else if (use1) pc = __fdividef((w1 < 0) ? 1.f : g_vec[(size_t)(w1 * 2 + b) * HW + r], Zv);
    }

    float o0a = 0.f, o0b = 0.f, o1a = 0.f, o1b = 0.f;
    uint32_t lbase = sbase + (lane & 7) * 176 + (lane >> 3) * 16;

    for (int t = 0; t < 2; t++) {
        if (t < 1) {
            #pragma unroll
            for (int k = 0; k < 4; k++) {
                int row = crow + k * 32;
                CP16(sbase + STAGE_B + row * 176 + cc16 * 16,
                     (const char*)&Qt[rbase + 128 + row][0] + cc16 * 16);
            }
            CPCOMMIT();
            CPWAIT1();
        } else {
            CPWAIT0();
        }
        if (tid < 128) cs0[t][tid] = pc;
        else if (use1) cs1[t][tid - 128] = pc;
        __syncthreads();
        if (t < 1) {
            int r = rbase + 128 + (tid & 127);
            float Zv = g_Z[zoff + r];
            if (tid < 128) pc = __fdividef((w0 < 0) ? 1.f : g_vec[(size_t)(w0 * 2 + b) * HW + r], Zv);
            else if (use1) pc = __fdividef((w1 < 0) ? 1.f : g_vec[(size_t)(w1 * 2 + b) * HW + r], Zv);
        }
        uint32_t tb = lbase + t * STAGE_B;
        const float* c0p = cs0[t];
        const float* c1p = cs1[t];
        #pragma unroll
        for (int nt = 0; nt < 16; nt++) {
            uint32_t bh[4], bl[4];
            uint32_t a = tb + nt * (8 * 176);
            ldsm4(bh, a);
            ldsm4(bl, a + 64);
            float c1[4] = {0.f, 0.f, 0.f, 0.f};
            float c2[4] = {0.f, 0.f, 0.f, 0.f};
            float c3[4] = {0.f, 0.f, 0.f, 0.f};
            LOGIT6(c1, c2, c3, afr, bh, bl);
            int il = nt * 8 + q * 2;
            float2 c0v = *(const float2*)&c0p[il];
            float e0 = ex2((c1[0] + c2[0]) + c3[0]);
            float e1 = ex2((c1[1] + c2[1]) + c3[1]);
            float e2 = ex2((c1[2] + c2[2]) + c3[2]);
            float e3 = ex2((c1[3] + c2[3]) + c3[3]);
            o0a = fmaf(c0v.x, e0, o0a); o0a = fmaf(c0v.y, e1, o0a);
            o0b = fmaf(c0v.x, e2, o0b); o0b = fmaf(c0v.y, e3, o0b);
            if (use1) {
                float2 c1v = *(const float2*)&c1p[il];
                o1a = fmaf(c1v.x, e0, o1a); o1a = fmaf(c1v.y, e1, o1a);
                o1b = fmaf(c1v.x, e2, o1b); o1b = fmaf(c1v.y, e3, o1b);
            }
        }
        __syncthreads();
    }
    o0a += __shfl_xor_sync(0xffffffffu, o0a, 1);
    o0a += __shfl_xor_sync(0xffffffffu, o0a, 2);
    o0b += __shfl_xor_sync(0xffffffffu, o0b, 1);
    o0b += __shfl_xor_sync(0xffffffffu, o0b, 2);
    if (use1) {
        o1a += __shfl_xor_sync(0xffffffffu, o1a, 1);
        o1a += __shfl_xor_sync(0xffffffffu, o1a, 2);
        o1b += __shfl_xor_sync(0xffffffffu, o1b, 1);
        o1b += __shfl_xor_sync(0xffffffffu, o1b, 2);
    }
    if (q == 0) {
        atomicAdd(&g_vec[(size_t)(o0i * 2 + b) * HW + jw + g], o0a);
        atomicAdd(&g_vec[(size_t)(o0i * 2 + b) * HW + jw + g + 8], o0b);
        if (use1) {
            atomicAdd(&g_vec[(size_t)(o1i * 2 + b) * HW + jw + g], o1a);
            atomicAdd(&g_vec[(size_t)(o1i * 2 + b) * HW + jw + g + 8], o1b);
        }
    }
}

// ---------------- broadcast result vectors (float4) ----------------
__global__ void __launch_bounds__(256) epilogue_kernel(float* __restrict__ out) {
    int id = blockIdx.x;
    int t = id >> 6, rem = id & 63;
    int b = rem >> 5, c = rem & 31;
    int vi = (t == 0) ? 7 : (t == 1) ? 6 : (t == 2) ? 4 : (t == 3) ? 3 : 1;
    const float4* v = (const float4*)(g_vec + (size_t)(vi * 2 + b) * HW);
    float4* o = (float4*)(out + (size_t)t * NB * 32 * HW + (size_t)b * 32 * HW + (size_t)c * HW);
    #pragma unroll
    for (int i = threadIdx.x; i < HW / 4; i += 256) o[i] = v[i];
}

extern "C" void kernel_launch(void* const* d_in, const int* in_sizes, int n_in,
                              void* d_out, int out_size)
{
    const float* x1 = (const float*)d_in[0];
    const float* x2 = (const float*)d_in[1];
    const float* x3 = (const float*)d_in[2];
    const float* W1 = (const float*)d_in[3];
    const float* g1 = (const float*)d_in[4];
    const float* b1 = (const float*)d_in[5];
    const float* W2 = (const float*)d_in[6];
    const float* g2 = (const float*)d_in[7];
    const float* b2 = (const float*)d_in[8];
    const float* W3 = (const float*)d_in[9];
    const float* g3 = (const float*)d_in[10];
    const float* b3 = (const float*)d_in[11];
    float* out = (float*)d_out;

    dim3 gp(32, 6);
    proj_kernel<<<gp, 256>>>(x1, x2, x3, W1, W2, W3);

    instnorm_kernel<<<576, 256>>>(g1, b1, g2, b2, g3, b3, out);

    split_kernel<<<dim3(32, 6), 256>>>();

    zt2_kernel<<<dim3(32, 8, 10), 256>>>();

    // A12 + A13 colsums merged (paired mode)
    bt2_kernel<<<dim3(32, 16, 4), 256>>>(-1, 0, 0, 0, 0);

    dim3 gb(32, 16, 2);
    bt2_kernel<<<gb, 256>>>(2, -1, 2,  0,  3);   // A23: colsum -> s23; s12@A23 -> t1
    bt2_kernel<<<gb, 256>>>(3,  2, 4,  3,  5);   // A32: s23@A32 -> p2; t1@A32 -> t2
    bt2_kernel<<<gb, 256>>>(4,  0, 6,  5,  7);   // A21: s12@A21 -> p1b; t2@A21 -> p1a

    epilogue_kernel<<<320, 256>>>(out);
}

// round 17
// speedup vs baseline: 1.0810x; 1.0810x over previous
#include <cuda_runtime.h>
#include <cuda_bf16.h>
#include <cstdint>

#define HW   4096
#define CIN  256
#define NB   2

// ---------------- device scratch ----------------
__device__ float g_y[6 * 96 * HW];
__device__ float g_Z[10 * HW];
__device__ float g_vec[16 * HW];
// bf16 split: t = (xi*2+b)*2 + role; role0=Q(*log2e), role1=K; row=[hi32|lo32]
__device__ __nv_bfloat16 g_T[12][HW][64];

static __device__ const int QX[5] = {0, 0, 1, 2, 1};
static __device__ const int KX[5] = {1, 2, 2, 1, 0};

__device__ __forceinline__ float ex2(float x) {
    float y; asm("ex2.approx.f32 %0, %1;" : "=f"(y) : "f"(x)); return y;
}
__device__ __forceinline__ void mma16816(float& d0, float& d1, float& d2, float& d3,
                                         const uint32_t* a, uint32_t b0, uint32_t b1) {
    asm volatile("mma.sync.aligned.m16n8k16.row.col.f32.bf16.bf16.f32 "
                 "{%0,%1,%2,%3}, {%4,%5,%6,%7}, {%8,%9}, {%0,%1,%2,%3};"
                 : "+f"(d0), "+f"(d1), "+f"(d2), "+f"(d3)
                 : "r"(a[0]), "r"(a[1]), "r"(a[2]), "r"(a[3]), "r"(b0), "r"(b1));
}
__device__ __forceinline__ void ldsm4(uint32_t* r, uint32_t a) {
    asm volatile("ldmatrix.sync.aligned.m8n8.x4.shared.b16 {%0,%1,%2,%3}, [%4];"
                 : "=r"(r[0]), "=r"(r[1]), "=r"(r[2]), "=r"(r[3]) : "r"(a));
}
#define CP16(d, s)  asm volatile("cp.async.cg.shared.global [%0], [%1], 16;" :: "r"(d), "l"(s))
#define CPCOMMIT()  asm volatile("cp.async.commit_group;")
#define CPWAIT1()   asm volatile("cp.async.wait_group 1;" ::: "memory")
#define CPWAIT0()   asm volatile("cp.async.wait_group 0;" ::: "memory")

#define STAGE_B 22528   // 128 rows * 176 bytes

// ---------------- projection (64-wide hw tiles; grid 64x6) ----------------
__global__ void __launch_bounds__(256) proj_kernel(
    const float* __restrict__ x1, const float* __restrict__ x2, const float* __restrict__ x3,
    const float* __restrict__ W1, const float* __restrict__ W2, const float* __restrict__ W3)
{
    int tile = blockIdx.x;
    int xb   = blockIdx.y;
    int xi = xb >> 1, b = xb & 1;
    const float* x = (xi == 0 ? x1 : xi == 1 ? x2 : x3) + (size_t)b * CIN * HW;

    __shared__ float sW[96][33];
    __shared__ float sX[32][64];

    int tid = threadIdx.x, tx = tid & 15, ty = tid >> 4;
    int hw0 = tile * 64;

    float acc[6][4];
    #pragma unroll
    for (int r = 0; r < 6; r++)
        #pragma unroll
        for (int c = 0; c < 4; c++) acc[r][c] = 0.f;

    for (int k0 = 0; k0 < CIN; k0 += 32) {
        __syncthreads();
        for (int i = tid; i < 96 * 8; i += 256) {
            int r = i >> 3, k4 = (i & 7) * 4;
            const float* Wp = (r < 32) ? W1 : (r < 64) ? W2 : W3;
            float4 v = *(const float4*)&Wp[(r & 31) * CIN + k0 + k4];
            sW[r][k4] = v.x; sW[r][k4 + 1] = v.y; sW[r][k4 + 2] = v.z; sW[r][k4 + 3] = v.w;
        }
        for (int i = tid; i < 32 * 16; i += 256) {
            int k = i >> 4, c4 = (i & 15) * 4;
            float4 v = *(const float4*)&x[(size_t)(k0 + k) * HW + hw0 + c4];
            *(float4*)&sX[k][c4] = v;
        }
        __syncthreads();
        #pragma unroll
        for (int k = 0; k < 32; k++) {
            float a[6], bb[4];
            #pragma unroll
            for (int r = 0; r < 6; r++) a[r] = sW[ty + 16 * r][k];
            #pragma unroll
            for (int c = 0; c < 4; c++) bb[c] = sX[k][tx + 16 * c];
            #pragma unroll
            for (int r = 0; r < 6; r++)
                #pragma unroll
                for (int c = 0; c < 4; c++) acc[r][c] = fmaf(a[r], bb[c], acc[r][c]);
        }
    }
    float* yp = g_y + (size_t)xb * 96 * HW;
    #pragma unroll
    for (int r = 0; r < 6; r++)
        #pragma unroll
        for (int c = 0; c < 4; c++)
            yp[(size_t)(ty + 16 * r) * HW + hw0 + tx + 16 * c] = acc[r][c];
}

// ---------------- instance norm + ReLU + V out + zero accums (float4) ----------------
__global__ void __launch_bounds__(256) instnorm_kernel(
    const float* __restrict__ g1, const float* __restrict__ b1,
    const float* __restrict__ g2, const float* __restrict__ b2,
    const float* __restrict__ g3, const float* __restrict__ b3,
    float* __restrict__ out)
{
    int id = blockIdx.x;
    int xb = id / 96, ch = id % 96;
    int xi = xb >> 1, b = xb & 1;
    float* row = g_y + (size_t)id * HW;
    float4* rowv = (float4*)row;
    int tid = threadIdx.x;

    {
        int n = 10 * HW + 16 * HW;
        for (int i = id * 256 + tid; i < n; i += 576 * 256) {
            if (i < 10 * HW) g_Z[i] = 0.f;
            else             g_vec[i - 10 * HW] = 0.f;
        }
    }

    float s = 0.f, s2 = 0.f;
    #pragma unroll
    for (int i = tid; i < HW / 4; i += 256) {
        float4 v = rowv[i];
        s += (v.x + v.y) + (v.z + v.w);
        s2 += (v.x * v.x + v.y * v.y) + (v.z * v.z + v.w * v.w);
    }
    #pragma unroll
    for (int o = 16; o; o >>= 1) {
        s  += __shfl_xor_sync(0xffffffffu, s,  o);
        s2 += __shfl_xor_sync(0xffffffffu, s2, o);
    }
    __shared__ float sh[16];
    __shared__ float sp[2];
    int w = tid >> 5;
    if ((tid & 31) == 0) { sh[w] = s; sh[8 + w] = s2; }
    __syncthreads();
    if (tid == 0) {
        float S = 0.f, S2 = 0.f;
        for (int k = 0; k < 8; k++) { S += sh[k]; S2 += sh[8 + k]; }
        float mean = S * (1.f / HW);
        float var  = S2 * (1.f / HW) - mean * mean;
        int br = ch / 32, c = ch & 31;
        const float* gp = br == 0 ? g1 : br == 1 ? g2 : g3;
        const float* bp = br == 0 ? b1 : br == 1 ? b2 : b3;
        float sc = gp[c] * rsqrtf(var + 1e-5f);
        sp[0] = sc;
        sp[1] = bp[c] - mean * sc;
    }
    __syncthreads();
    float sc = sp[0], sf = sp[1];
    bool isv = (ch >= 64);
    float4* voutv = (float4*)(out + (size_t)(5 + xi) * NB * 32 * HW + (size_t)b * 32 * HW
                              + (size_t)(ch - 64) * HW);
    #pragma unroll
    for (int i = tid; i < HW / 4; i += 256) {
        float4 v = rowv[i];
        v.x = fmaxf(fmaf(v.x, sc, sf), 0.f);
        v.y = fmaxf(fmaf(v.y, sc, sf), 0.f);
        v.z = fmaxf(fmaf(v.z, sc, sf), 0.f);
        v.w = fmaxf(fmaf(v.w, sc, sf), 0.f);
        rowv[i] = v;
        if (isv) voutv[i] = v;
    }
}

// ---------------- bf16 hi/lo split (64-wide tiles; grid 64x6) ----------------
__global__ void __launch_bounds__(256) split_kernel() {
    int xb = blockIdx.y;
    int i0 = blockIdx.x * 64;
    __shared__ float s[64][65];
    const float* src = g_y + (size_t)xb * 96 * HW;
    for (int idx = threadIdx.x; idx < 64 * 16; idx += 256) {
        int ch = idx >> 4, i = (idx & 15) * 4;
        float4 v = *(const float4*)&src[(size_t)ch * HW + i0 + i];
        s[ch][i] = v.x; s[ch][i + 1] = v.y; s[ch][i + 2] = v.z; s[ch][i + 3] = v.w;
    }
    __syncthreads();
    const float LOG2E = 1.4426950408889634f;
    for (int idx = threadIdx.x; idx < 64 * 32; idx += 256) {
        int r = idx >> 5, c = idx & 31;
        float q = s[c][r] * LOG2E;
        __nv_bfloat16 qh = __float2bfloat16(q);
        __nv_bfloat16 ql = __float2bfloat16(q - __bfloat162float(qh));
        __nv_bfloat16* qrow = &g_T[xb * 2 + 0][i0 + r][0];
        qrow[c] = qh; qrow[32 + c] = ql;
        float kv = s[32 + c][r];
        __nv_bfloat16 kh = __float2bfloat16(kv);
        __nv_bfloat16 kl = __float2bfloat16(kv - __bfloat162float(kh));
        __nv_bfloat16* krow = &g_T[xb * 2 + 1][i0 + r][0];
        krow[c] = kh; krow[32 + c] = kl;
    }
}

// ---------------- Z pass: grid (32 row tiles, 8 col groups, 10 mb); R15 exact ----------------
__global__ void __launch_bounds__(256) zt2_kernel() {
    __shared__ __nv_bfloat16 sK[2][128][88];   // double buffer, 176B rows

    int tid = threadIdx.x, wid = tid >> 5, lane = tid & 31;
    int q = lane & 3, g = lane >> 2;
    int mb = blockIdx.z, m = mb >> 1, b = mb & 1;
    int r0 = blockIdx.x * 128, c0 = blockIdx.y * 512;     // 4 tiles of 128 cols

    const __nv_bfloat16 (*Qt)[64] = g_T[(QX[m] * 2 + b) * 2 + 0];
    const __nv_bfloat16 (*Kt)[64] = g_T[(KX[m] * 2 + b) * 2 + 1];

    int rw = r0 + wid * 16;
    uint32_t afr[2][2][4];
    #pragma unroll
    for (int p = 0; p < 2; p++)
        #pragma unroll
        for (int c = 0; c < 2; c++) {
            int col = p * 32 + c * 16 + q * 2;
            afr[p][c][0] = *(const uint32_t*)&Qt[rw + g][col];
            afr[p][c][1] = *(const uint32_t*)&Qt[rw + g + 8][col];
            afr[p][c][2] = *(const uint32_t*)&Qt[rw + g][col + 8];
            afr[p][c][3] = *(const uint32_t*)&Qt[rw + g + 8][col + 8];
        }

    uint32_t sbase = (uint32_t)__cvta_generic_to_shared(&sK[0][0][0]);
    int crow = tid >> 3, cc16 = tid & 7;

    #pragma unroll
    for (int k = 0; k < 4; k++) {
        int row = crow + k * 32;
        CP16(sbase + row * 176 + cc16 * 16,
             (const char*)&Kt[c0 + row][0] + cc16 * 16);
    }
    CPCOMMIT();

    float za0 = 0.f, za1 = 0.f;
    uint32_t lbase = sbase + (lane & 7) * 176 + (lane >> 3) * 16;

    for (int t = 0; t < 4; t++) {
        if (t < 3) {
            int buf = (t + 1) & 1;
            #pragma unroll
            for (int k = 0; k < 4; k++) {
                int row = crow + k * 32;
                CP16(sbase + buf * STAGE_B + row * 176 + cc16 * 16,
                     (const char*)&Kt[c0 + (t + 1) * 128 + row][0] + cc16 * 16);
            }
            CPCOMMIT();
            CPWAIT1();
        } else {
            CPWAIT0();
        }
        __syncthreads();
        uint32_t tb = lbase + (t & 1) * STAGE_B;
        #pragma unroll
        for (int nt = 0; nt < 16; nt++) {
            uint32_t bh[4], bl[4];
            uint32_t a = tb + nt * (8 * 176);
            ldsm4(bh, a);
            ldsm4(bl, a + 64);
            float dA0 = 0.f, dA1 = 0.f, dA2 = 0.f, dA3 = 0.f;
            float dB0 = 0.f, dB1 = 0.f, dB2 = 0.f, dB3 = 0.f;
            mma16816(dA0, dA1, dA2, dA3, afr[0][0], bh[0], bh[1]);
            mma16816(dB0, dB1, dB2, dB3, afr[0][1], bh[2], bh[3]);
            mma16816(dA0, dA1, dA2, dA3, afr[0][0], bl[0], bl[1]);
            mma16816(dB0, dB1, dB2, dB3, afr[0][1], bl[2], bl[3]);
            mma16816(dA0, dA1, dA2, dA3, afr[1][0], bh[0], bh[1]);
            mma16816(dB0, dB1, dB2, dB3, afr[1][1], bh[2], bh[3]);
            float e0 = ex2(dA0 + dB0), e1 = ex2(dA1 + dB1);
            float e2 = ex2(dA2 + dB2), e3 = ex2(dA3 + dB3);
            za0 += e0 + e1;
            za1 += e2 + e3;
        }
        __syncthreads();
    }
    za0 += __shfl_xor_sync(0xffffffffu, za0, 1);
    za0 += __shfl_xor_sync(0xffffffffu, za0, 2);
    za1 += __shfl_xor_sync(0xffffffffu, za1, 1);
    za1 += __shfl_xor_sync(0xffffffffu, za1, 2);
    if (q == 0) {
        atomicAdd(&g_Z[(size_t)mb * HW + rw + g], za0);
        atomicAdd(&g_Z[(size_t)mb * HW + rw + g + 8], za1);
    }
}

// ---------------- weighted colsum: grid (32 j-strips, 16 row groups, 2|4); R15 exact -----
// m < 0: paired mode — blockIdx.z encodes (mm,b), colsum-only into vec mm (A12/A13).
__global__ void __launch_bounds__(256) bt2_kernel(int m, int w0, int o0i, int w1, int o1i) {
    __shared__ __nv_bfloat16 sQ[2][128][88];
    __shared__ float cs0[2][128];
    __shared__ float cs1[2][128];

    int tid = threadIdx.x, wid = tid >> 5, lane = tid & 31;
    int q = lane & 3, g = lane >> 2;
    int b;
    if (m < 0) {
        int mz = blockIdx.z;
        b = mz & 1;
        m = mz >> 1;
        w0 = -1; o0i = m; o1i = -1;
    } else {
        b = blockIdx.z;
    }
    int j0 = blockIdx.x * 128, rbase = blockIdx.y * 256;   // 2 tiles of 128 rows
    bool use1 = (o1i >= 0);
    size_t zoff = (size_t)(m * 2 + b) * HW;

    const __nv_bfloat16 (*Qt)[64] = g_T[(QX[m] * 2 + b) * 2 + 0];
    const __nv_bfloat16 (*Kt)[64] = g_T[(KX[m] * 2 + b) * 2 + 1];

    int jw = j0 + wid * 16;
    uint32_t afr[2][2][4];
    #pragma unroll
    for (int p = 0; p < 2; p++)
        #pragma unroll
        for (int c = 0; c < 2; c++) {
            int col = p * 32 + c * 16 + q * 2;
            afr[p][c][0] = *(const uint32_t*)&Kt[jw + g][col];
            afr[p][c][1] = *(const uint32_t*)&Kt[jw + g + 8][col];
            afr[p][c][2] = *(const uint32_t*)&Kt[jw + g][col + 8];
            afr[p][c][3] = *(const uint32_t*)&Kt[jw + g + 8][col + 8];
        }

    uint32_t sbase = (uint32_t)__cvta_generic_to_shared(&sQ[0][0][0]);
    int crow = tid >> 3, cc16 = tid & 7;

    #pragma unroll
    for (int k = 0; k < 4; k++) {
        int row = crow + k * 32;
        CP16(sbase + row * 176 + cc16 * 16,
             (const char*)&Qt[rbase + row][0] + cc16 * 16);
    }
    CPCOMMIT();

    float pc = 0.f;
    {
        int r = rbase + (tid & 127);
        float Zv = g_Z[zoff + r];
        if (tid < 128) pc = __fdividef((w0 < 0) ? 1.f : g_vec[(size_t)(w0 * 2 + b) * HW + r], Zv);
        else if (use1) pc = __fdividef((w1 < 0) ? 1.f : g_vec[(size_t)(w1 * 2 + b) * HW + r], Zv);
    }

    float o0a = 0.f, o0b = 0.f, o1a = 0.f, o1b = 0.f;
    uint32_t lbase = sbase + (lane & 7) * 176 + (lane >> 3) * 16;

    for (int t = 0; t < 2; t++) {
        if (t < 1) {
            #pragma unroll
            for (int k = 0; k < 4; k++) {
                int row = crow + k * 32;
                CP16(sbase + STAGE_B + row * 176 + cc16 * 16,
                     (const char*)&Qt[rbase + 128 + row][0] + cc16 * 16);
            }
            CPCOMMIT();
            CPWAIT1();
        } else {
            CPWAIT0();
        }
        if (tid < 128) cs0[t][tid] = pc;
        else if (use1) cs1[t][tid - 128] = pc;
        __syncthreads();
        if (t < 1) {
            int r = rbase + 128 + (tid & 127);
            float Zv = g_Z[zoff + r];
            if (tid < 128) pc = __fdividef((w0 < 0) ? 1.f : g_vec[(size_t)(w0 * 2 + b) * HW + r], Zv);
            else if (use1) pc = __fdividef((w1 < 0) ? 1.f : g_vec[(size_t)(w1 * 2 + b) * HW + r], Zv);
        }
        uint32_t tb = lbase + t * STAGE_B;
        const float* c0p = cs0[t];
        const float* c1p = cs1[t];
        #pragma unroll
        for (int nt = 0; nt < 16; nt++) {
            uint32_t bh[4], bl[4];
            uint32_t a = tb + nt * (8 * 176);
            ldsm4(bh, a);
            ldsm4(bl, a + 64);
            float dA0 = 0.f, dA1 = 0.f, dA2 = 0.f, dA3 = 0.f;
            float dB0 = 0.f, dB1 = 0.f, dB2 = 0.f, dB3 = 0.f;
            mma16816(dA0, dA1, dA2, dA3, afr[0][0], bh[0], bh[1]);
            mma16816(dB0, dB1, dB2, dB3, afr[0][1], bh[2], bh[3]);
            mma16816(dA0, dA1, dA2, dA3, afr[0][0], bl[0], bl[1]);
            mma16816(dB0, dB1, dB2, dB3, afr[0][1], bl[2], bl[3]);
            mma16816(dA0, dA1, dA2, dA3, afr[1][0], bh[0], bh[1]);
            mma16816(dB0, dB1, dB2, dB3, afr[1][1], bh[2], bh[3]);
            int il = nt * 8 + q * 2;
            float2 c0v = *(const float2*)&c0p[il];
            float e0 = ex2(dA0 + dB0), e1 = ex2(dA1 + dB1);
            float e2 = ex2(dA2 + dB2), e3 = ex2(dA3 + dB3);
            o0a = fmaf(c0v.x, e0, o0a); o0a = fmaf(c0v.y, e1, o0a);
            o0b = fmaf(c0v.x, e2, o0b); o0b = fmaf(c0v.y, e3, o0b);
            if (use1) {
                float2 c1v = *(const float2*)&c1p[il];
                o1a = fmaf(c1v.x, e0, o1a); o1a = fmaf(c1v.y, e1, o1a);
                o1b = fmaf(c1v.x, e2, o1b); o1b = fmaf(c1v.y, e3, o1b);
            }
        }
        __syncthreads();
    }
    o0a += __shfl_xor_sync(0xffffffffu, o0a, 1);
    o0a += __shfl_xor_sync(0xffffffffu, o0a, 2);
    o0b += __shfl_xor_sync(0xffffffffu, o0b, 1);
    o0b += __shfl_xor_sync(0xffffffffu, o0b, 2);
    if (use1) {
        o1a += __shfl_xor_sync(0xffffffffu, o1a, 1);
        o1a += __shfl_xor_sync(0xffffffffu, o1a, 2);
        o1b += __shfl_xor_sync(0xffffffffu, o1b, 1);
        o1b += __shfl_xor_sync(0xffffffffu, o1b, 2);
    }
    if (q == 0) {
        atomicAdd(&g_vec[(size_t)(o0i * 2 + b) * HW + jw + g], o0a);
        atomicAdd(&g_vec[(size_t)(o0i * 2 + b) * HW + jw + g + 8], o0b);
        if (use1) {
            atomicAdd(&g_vec[(size_t)(o1i * 2 + b) * HW + jw + g], o1a);
            atomicAdd(&g_vec[(size_t)(o1i * 2 + b) * HW + jw + g + 8], o1b);
        }
    }
}

// ---------------- broadcast result vectors (float4) ----------------
__global__ void __launch_bounds__(256) epilogue_kernel(float* __restrict__ out) {
    int id = blockIdx.x;
    int t = id >> 6, rem = id & 63;
    int b = rem >> 5, c = rem & 31;
    int vi = (t == 0) ? 7 : (t == 1) ? 6 : (t == 2) ? 4 : (t == 3) ? 3 : 1;
    const float4* v = (const float4*)(g_vec + (size_t)(vi * 2 + b) * HW);
    float4* o = (float4*)(out + (size_t)t * NB * 32 * HW + (size_t)b * 32 * HW + (size_t)c * HW);
    #pragma unroll
    for (int i = threadIdx.x; i < HW / 4; i += 256) o[i] = v[i];
}

extern "C" void kernel_launch(void* const* d_in, const int* in_sizes, int n_in,
                              void* d_out, int out_size)
{
    const float* x1 = (const float*)d_in[0];
    const float* x2 = (const float*)d_in[1];
    const float* x3 = (const float*)d_in[2];
    const float* W1 = (const float*)d_in[3];
    const float* g1 = (const float*)d_in[4];
    const float* b1 = (const float*)d_in[5];
    const float* W2 = (const float*)d_in[6];
    const float* g2 = (const float*)d_in[7];
    const float* b2 = (const float*)d_in[8];
    const float* W3 = (const float*)d_in[9];
    const float* g3 = (const float*)d_in[10];
    const float* b3 = (const float*)d_in[11];
    float* out = (float*)d_out;

    proj_kernel<<<dim3(64, 6), 256>>>(x1, x2, x3, W1, W2, W3);

    instnorm_kernel<<<576, 256>>>(g1, b1, g2, b2, g3, b3, out);

    split_kernel<<<dim3(64, 6), 256>>>();

    zt2_kernel<<<dim3(32, 8, 10), 256>>>();

    // A12 + A13 colsums merged (paired mode)
    bt2_kernel<<<dim3(32, 16, 4), 256>>>(-1, 0, 0, 0, 0);

    dim3 gb(32, 16, 2);
    bt2_kernel<<<gb, 256>>>(2, -1, 2,  0,  3);   // A23: colsum -> s23; s12@A23 -> t1
    bt2_kernel<<<gb, 256>>>(3,  2, 4,  3,  5);   // A32: s23@A32 -> p2; t1@A32 -> t2
    bt2_kernel<<<gb, 256>>>(4,  0, 6,  5,  7);   // A21: s12@A21 -> p1b; t2@A21 -> p1a

    epilogue_kernel<<<320, 256>>>(out);
}